// round 6
// baseline (speedup 1.0000x reference)
#include <cuda_runtime.h>
#include <math.h>

// B=32, C=32, H=64, W=64, pool 2x2 -> 32x32 pooled positions per (c).
// One WARP per (c,h2) slab: lane = pooled w2, loop over batch i.
// Closed form per position via 10 linear batch-sums -> no smem, no barriers in hot loop.
// Grid: 256 blocks x 128 threads = 1024 warps = 32 c x 32 h2.

__device__ double g_part[256];
__device__ unsigned int g_count = 0;   // self-resetting

__global__ __launch_bounds__(128) void k_main(
    const float* __restrict__ mu_a, const float* __restrict__ lv_a,
    const float* __restrict__ mu_b, const float* __restrict__ lv_b,
    float* __restrict__ out)
{
    const int t    = threadIdx.x;
    const int lane = t & 31;
    const int w    = blockIdx.x * 4 + (t >> 5);   // global warp id 0..1023
    const int c    = w >> 5;
    const int h2   = w & 31;

    // lane owns pooled position (c, h2, w2=lane); rows 2*h2 and 2*h2+1, cols 2*lane..2*lane+1
    int ofs = (c * 64 + 2 * h2) * 64 + 2 * lane;
    const int istride = 32 * 64 * 64;             // batch stride in floats

    float S1 = 0.f, S2 = 0.f, S3 = 0.f, L = 0.f;
    float U0a = 0.f, U1a = 0.f, U2a = 0.f;
    float U0b = 0.f, U1b = 0.f, U2b = 0.f;
    const float s2pi = 2.5066282746310002f;       // sqrt(2*pi)

    #pragma unroll 4
    for (int i = 0; i < 32; i++) {
        float2 A0  = *(const float2*)(mu_a + ofs);
        float2 A1  = *(const float2*)(mu_a + ofs + 64);
        float2 La0 = *(const float2*)(lv_a + ofs);
        float2 La1 = *(const float2*)(lv_a + ofs + 64);
        float2 B0  = *(const float2*)(mu_b + ofs);
        float2 B1  = *(const float2*)(mu_b + ofs + 64);
        float2 Lb0 = *(const float2*)(lv_b + ofs);
        float2 Lb1 = *(const float2*)(lv_b + ofs + 64);
        ofs += istride;

        float ma = (A0.x + A0.y + A1.x + A1.y) * 0.25f;
        float va = (__expf(La0.x) + __expf(La0.y) + __expf(La1.x) + __expf(La1.y)) * 0.0625f;
        float mb = (B0.x + B0.y + B1.x + B1.y) * 0.25f;
        float vb = (__expf(Lb0.x) + __expf(Lb0.y) + __expf(Lb1.x) + __expf(Lb1.y)) * 0.0625f;

        float ma2 = ma * ma, va2 = va * va;
        float mb2 = mb * mb, vb2 = vb * vb;
        S1 += ma; S2 += ma2; S3 += va2;

        float ra = __fdividef(1.0f, va2);
        float rb = __fdividef(1.0f, vb2);
        U0a += ra;  U1a += ma * ra;  U2a += ma2 * ra;
        U0b += rb;  U1b += mb * rb;  U2b += mb2 * rb;

        float la = __logf(__fdividef(1.0f, va * s2pi) + 1e-6f);
        float lb = __logf(__fdividef(1.0f, vb * s2pi) + 1e-6f);
        L += la - lb;
    }

    // Per-position combine:
    // sum_ij diff = 32*L - [0.5*(S2+S3)*U0a - S1*U1a + 16*U2a]
    //             +        [0.5*(S2+S3)*U0b - S1*U1b + 16*U2b]
    float SS = S2 + S3;
    float pa = 0.5f * SS * U0a - S1 * U1a + 16.0f * U2a;
    float pb = 0.5f * SS * U0b - S1 * U1b + 16.0f * U2b;
    double contrib = 32.0 * (double)L - (double)pa + (double)pb;

    // Warp reduce over the 32 positions (lanes)
    #pragma unroll
    for (int o = 16; o; o >>= 1)
        contrib += __shfl_xor_sync(0xffffffffu, contrib, o);

    __shared__ double s_w[4];
    __shared__ bool s_last;
    if (lane == 0) s_w[t >> 5] = contrib;
    __syncthreads();

    if (t == 0) {
        double s = s_w[0] + s_w[1] + s_w[2] + s_w[3];
        g_part[blockIdx.x] = s;
        __threadfence();
        unsigned int prev = atomicInc(&g_count, 0xffffffffu);
        s_last = (prev == gridDim.x - 1);
    }
    __syncthreads();

    if (s_last) {
        // 128 threads reduce 256 partials
        double v = g_part[t] + g_part[t + 128];
        #pragma unroll
        for (int o = 16; o; o >>= 1)
            v += __shfl_xor_sync(0xffffffffu, v, o);
        __shared__ double s_f[4];
        if (lane == 0) s_f[t >> 5] = v;
        __syncthreads();
        if (t == 0) {
            out[0] = (float)((s_f[0] + s_f[1] + s_f[2] + s_f[3]) * (1.0 / 1024.0)); // /(B*B)
            g_count = 0;   // reset for next graph replay
        }
    }
}

extern "C" void kernel_launch(void* const* d_in, const int* in_sizes, int n_in,
                              void* d_out, int out_size) {
    const float* mu_a = (const float*)d_in[0];
    const float* lv_a = (const float*)d_in[1];
    const float* mu_b = (const float*)d_in[2];
    const float* lv_b = (const float*)d_in[3];

    k_main<<<256, 128>>>(mu_a, lv_a, mu_b, lv_b, (float*)d_out);
}

// round 7
// speedup vs baseline: 1.9617x; 1.9617x over previous
#include <cuda_runtime.h>
#include <math.h>

// B=32, C=32, H=64, W=64, pool 2x2 -> 32x32 pooled positions per channel.
// Block (128 thr, 4 warps) owns one (c, h2) slab; lane = pooled w2.
// Warp q accumulates the 10 linear batch-sums over i in [8q, 8q+8) -- no barriers
// in the hot loop. One smem merge + nonlinear combine at the end.

__device__ double g_part[1024];
__device__ unsigned int g_count = 0;   // self-resetting

__global__ __launch_bounds__(128, 8) void k_main(
    const float* __restrict__ mu_a, const float* __restrict__ lv_a,
    const float* __restrict__ mu_b, const float* __restrict__ lv_b,
    float* __restrict__ out)
{
    __shared__ float s_p[4][32][10];   // [warp][lane=w2][sum]
    __shared__ bool  s_last;

    const int t    = threadIdx.x;
    const int lane = t & 31;           // w2
    const int wq   = t >> 5;           // batch chunk 0..3
    const int b    = blockIdx.x;
    const int c    = b >> 5;
    const int h2   = b & 31;

    // first element for i = 8*wq at (c, 2*h2, 2*lane)
    const int istride = 32 * 64 * 64;
    int ofs = (8 * wq) * istride + (c * 64 + 2 * h2) * 64 + 2 * lane;

    float S1 = 0.f, S2 = 0.f, S3 = 0.f, L = 0.f;
    float U0a = 0.f, U1a = 0.f, U2a = 0.f;
    float U0b = 0.f, U1b = 0.f, U2b = 0.f;
    const float s2pi = 2.5066282746310002f;   // sqrt(2*pi)

    #pragma unroll 2
    for (int i = 0; i < 8; i++) {
        float2 A0  = *(const float2*)(mu_a + ofs);
        float2 A1  = *(const float2*)(mu_a + ofs + 64);
        float2 La0 = *(const float2*)(lv_a + ofs);
        float2 La1 = *(const float2*)(lv_a + ofs + 64);
        float2 B0  = *(const float2*)(mu_b + ofs);
        float2 B1  = *(const float2*)(mu_b + ofs + 64);
        float2 Lb0 = *(const float2*)(lv_b + ofs);
        float2 Lb1 = *(const float2*)(lv_b + ofs + 64);
        ofs += istride;

        float ma = (A0.x + A0.y + A1.x + A1.y) * 0.25f;
        float va = (__expf(La0.x) + __expf(La0.y) + __expf(La1.x) + __expf(La1.y)) * 0.0625f;
        float mb = (B0.x + B0.y + B1.x + B1.y) * 0.25f;
        float vb = (__expf(Lb0.x) + __expf(Lb0.y) + __expf(Lb1.x) + __expf(Lb1.y)) * 0.0625f;

        float ma2 = ma * ma, va2 = va * va;
        float mb2 = mb * mb, vb2 = vb * vb;
        S1 += ma; S2 += ma2; S3 += va2;

        float ra = __fdividef(1.0f, va2);
        float rb = __fdividef(1.0f, vb2);
        U0a += ra;  U1a += ma * ra;  U2a += ma2 * ra;
        U0b += rb;  U1b += mb * rb;  U2b += mb2 * rb;

        float la = __logf(__fdividef(1.0f, va * s2pi) + 1e-6f);
        float lb = __logf(__fdividef(1.0f, vb * s2pi) + 1e-6f);
        L += la - lb;
    }

    // publish partial sums
    s_p[wq][lane][0] = S1;  s_p[wq][lane][1] = S2;  s_p[wq][lane][2] = S3;
    s_p[wq][lane][3] = U0a; s_p[wq][lane][4] = U1a; s_p[wq][lane][5] = U2a;
    s_p[wq][lane][6] = U0b; s_p[wq][lane][7] = U1b; s_p[wq][lane][8] = U2b;
    s_p[wq][lane][9] = L;
    __syncthreads();

    if (wq == 0) {
        float m[10];
        #pragma unroll
        for (int k = 0; k < 10; k++)
            m[k] = s_p[0][lane][k] + s_p[1][lane][k] + s_p[2][lane][k] + s_p[3][lane][k];

        // sum_ij diff = 32*L - [0.5*(S2+S3)*U0a - S1*U1a + 16*U2a]
        //                    + [0.5*(S2+S3)*U0b - S1*U1b + 16*U2b]
        float SS = m[1] + m[2];
        float pa = 0.5f * SS * m[3] - m[0] * m[4] + 16.0f * m[5];
        float pb = 0.5f * SS * m[6] - m[0] * m[7] + 16.0f * m[8];
        double contrib = 32.0 * (double)m[9] - (double)pa + (double)pb;

        #pragma unroll
        for (int o = 16; o; o >>= 1)
            contrib += __shfl_xor_sync(0xffffffffu, contrib, o);

        if (lane == 0) {
            g_part[b] = contrib;
            __threadfence();
            unsigned int prev = atomicInc(&g_count, 0xffffffffu);
            s_last = (prev == gridDim.x - 1);
        }
    }
    __syncthreads();

    if (s_last) {
        // 128 threads reduce 1024 partials: 8 each, then tree.
        double v = 0.0;
        #pragma unroll
        for (int k = 0; k < 8; k++) v += g_part[t + 128 * k];
        #pragma unroll
        for (int o = 16; o; o >>= 1)
            v += __shfl_xor_sync(0xffffffffu, v, o);
        __shared__ double s_f[4];
        if ((t & 31) == 0) s_f[t >> 5] = v;
        __syncthreads();
        if (t == 0) {
            out[0] = (float)((s_f[0] + s_f[1] + s_f[2] + s_f[3]) * (1.0 / 1024.0)); // /(B*B)
            g_count = 0;   // reset for next graph replay
        }
    }
}

extern "C" void kernel_launch(void* const* d_in, const int* in_sizes, int n_in,
                              void* d_out, int out_size) {
    const float* mu_a = (const float*)d_in[0];
    const float* lv_a = (const float*)d_in[1];
    const float* mu_b = (const float*)d_in[2];
    const float* lv_b = (const float*)d_in[3];

    k_main<<<1024, 128>>>(mu_a, lv_a, mu_b, lv_b, (float*)d_out);
}